// round 1
// baseline (speedup 1.0000x reference)
#include <cuda_runtime.h>
#include <math.h>
#include <float.h>

// Problem-fixed sizes (match metadata)
#define NN 100000
#define BB 64
#define EE 1600000
#define DH 128
#define NCLS 3
#define TOLV 1e-7f
#define BN_EPSV 1e-5f
#define MIN_SCORE 0.1f

#define KBWORDS ((NN + 31) / 32)

// ---------------- device scratch (no allocations allowed) ----------------
__device__ float g_logit[NN];
__device__ float g_score[NN];
__device__ float g_gmax[BB];
__device__ float g_gsum[BB];
__device__ float g_smax[BB];
__device__ int   g_nk;
__device__ int   g_nce;
__device__ int   g_kidx[NN];          // compact pos -> node id
__device__ int   g_cidx[NN];          // node id -> compact pos (valid only for kept)
__device__ unsigned g_kbits[KBWORDS]; // keep bitmask
__device__ float g_h0[NN * 2];        // compact layer-0 features (x * score)
__device__ int   g_esrc[EE];          // compact edges (compact indices)
__device__ int   g_edst[EE];
__device__ float g_degc[NN];          // compact degree (edge count)
__device__ float g_dinv[NN];
__device__ float g_selfn[NN];
__device__ float g_agg[NN * DH];
__device__ float g_hA[NN * DH];
__device__ float g_hB[NN * DH];
__device__ float g_pool[BB * DH];

__device__ __forceinline__ void atomicMaxF(float* addr, float v) {
    if (v >= 0.0f) atomicMax((int*)addr, __float_as_int(v));
    else           atomicMin((unsigned int*)addr, __float_as_uint(v));
}

// ---------------- kernels ----------------
__global__ void k_init() {
    int i = blockIdx.x * blockDim.x + threadIdx.x;
    if (i < NN) g_degc[i] = 0.0f;
    if (i < KBWORDS) g_kbits[i] = 0u;
    if (i < BB) { g_gmax[i] = -FLT_MAX; g_gsum[i] = 0.0f; g_smax[i] = -FLT_MAX; }
    if (i < BB * DH) g_pool[i] = -FLT_MAX;
    if (i == 0) { g_nk = 0; g_nce = 0; }
}

__global__ void k_logit(const float* __restrict__ x, const float* __restrict__ w,
                        const int* __restrict__ batch) {
    int i = blockIdx.x * blockDim.x + threadIdx.x;
    if (i >= NN) return;
    float l = x[2 * i] * w[0] + x[2 * i + 1] * w[1];
    g_logit[i] = l;
    atomicMaxF(&g_gmax[batch[i]], l);
}

__global__ void k_exp(const int* __restrict__ batch) {
    int i = blockIdx.x * blockDim.x + threadIdx.x;
    if (i >= NN) return;
    int b = batch[i];
    float e = expf(g_logit[i] - g_gmax[b]);
    g_score[i] = e;
    atomicAdd(&g_gsum[b], e);
}

__global__ void k_score(const int* __restrict__ batch) {
    int i = blockIdx.x * blockDim.x + threadIdx.x;
    if (i >= NN) return;
    int b = batch[i];
    float s = g_score[i] / g_gsum[b];
    g_score[i] = s;
    atomicMaxF(&g_smax[b], s);
}

__global__ void k_keep(const float* __restrict__ x, const int* __restrict__ batch) {
    int i = blockIdx.x * blockDim.x + threadIdx.x;
    if (i >= NN) return;
    int b = batch[i];
    float thr = fminf(g_smax[b] - TOLV, MIN_SCORE);
    float s = g_score[i];
    if (s > thr) {
        int pos = atomicAdd(&g_nk, 1);
        g_kidx[pos] = i;
        g_cidx[i] = pos;
        atomicOr(&g_kbits[i >> 5], 1u << (i & 31));
        g_h0[pos * 2 + 0] = x[2 * i] * s;
        g_h0[pos * 2 + 1] = x[2 * i + 1] * s;
    }
}

__global__ void k_edges(const int* __restrict__ ei) {
    int e = blockIdx.x * blockDim.x + threadIdx.x;
    if (e >= EE) return;
    int s = ei[e];
    int d = ei[EE + e];
    unsigned bs = g_kbits[s >> 5] >> (s & 31);
    unsigned bd = g_kbits[d >> 5] >> (d & 31);
    if (bs & bd & 1u) {
        int pos = atomicAdd(&g_nce, 1);
        int cs = g_cidx[s];
        int cd = g_cidx[d];
        g_esrc[pos] = cs;
        g_edst[pos] = cd;
        atomicAdd(&g_degc[cd], 1.0f);
    }
}

__global__ void k_dinv() {
    int nk = g_nk;
    for (int p = blockIdx.x * blockDim.x + threadIdx.x; p < nk;
         p += gridDim.x * blockDim.x) {
        float deg = g_degc[p] + 1.0f;  // + self-loop (keep_f == 1 for kept)
        float di = rsqrtf(deg);
        g_dinv[p] = di;
        g_selfn[p] = di * di;
    }
}

template <int D>
__global__ void k_aggself(const float* __restrict__ h) {
    int total = g_nk * D;
    for (int t = blockIdx.x * blockDim.x + threadIdx.x; t < total;
         t += gridDim.x * blockDim.x) {
        int p = t / D;
        g_agg[t] = g_selfn[p] * h[t];
    }
}

template <int D>
__global__ void k_aggedge(const float* __restrict__ h) {
    int total = g_nce * D;
    for (int t = blockIdx.x * blockDim.x + threadIdx.x; t < total;
         t += gridDim.x * blockDim.x) {
        int e = t / D;
        int j = t - e * D;
        int cs = g_esrc[e];
        int cd = g_edst[e];
        float w = g_dinv[cs] * g_dinv[cd];
        atomicAdd(&g_agg[cd * D + j], w * h[cs * D + j]);
    }
}

// layer 1: din=2 -> 128, fused bias+relu+bn
__global__ void k_gemm1(const float* __restrict__ W, const float* __restrict__ b,
                        const float* __restrict__ g, const float* __restrict__ be,
                        const float* __restrict__ rm, const float* __restrict__ rv,
                        float* __restrict__ out) {
    int nk = g_nk;
    int j = threadIdx.x;  // 0..127
    for (int p = blockIdx.x; p < nk; p += gridDim.x) {
        float v = g_agg[p * 2] * W[j] + g_agg[p * 2 + 1] * W[DH + j] + b[j];
        v = fmaxf(v, 0.0f);
        v = (v - rm[j]) * rsqrtf(rv[j] + BN_EPSV) * g[j] + be[j];
        out[p * DH + j] = v;
    }
}

// layers 2/3: 128 -> 128, fused bias+relu+bn
__global__ void k_gemm128(const float* __restrict__ W, const float* __restrict__ b,
                          const float* __restrict__ g, const float* __restrict__ be,
                          const float* __restrict__ rm, const float* __restrict__ rv,
                          float* __restrict__ out) {
    __shared__ float srow[DH];
    int nk = g_nk;
    int j = threadIdx.x;  // 0..127
    for (int p = blockIdx.x; p < nk; p += gridDim.x) {
        srow[j] = g_agg[p * DH + j];
        __syncthreads();
        float v = b[j];
        #pragma unroll 8
        for (int k = 0; k < DH; k++) v = fmaf(srow[k], W[k * DH + j], v);
        v = fmaxf(v, 0.0f);
        v = (v - rm[j]) * rsqrtf(rv[j] + BN_EPSV) * g[j] + be[j];
        out[p * DH + j] = v;
        __syncthreads();
    }
}

__global__ void k_pool(const int* __restrict__ batch, const float* __restrict__ h) {
    int total = g_nk * DH;
    for (int t = blockIdx.x * blockDim.x + threadIdx.x; t < total;
         t += gridDim.x * blockDim.x) {
        int p = t / DH;
        int j = t - p * DH;
        int b = batch[g_kidx[p]];
        atomicMaxF(&g_pool[b * DH + j], h[t]);
    }
}

__global__ void k_final(const float* __restrict__ linW, const float* __restrict__ linb,
                        float* __restrict__ out) {
    int b = threadIdx.x;
    if (b >= BB) return;
    float z[NCLS];
    for (int c = 0; c < NCLS; c++) z[c] = linb[c];
    for (int j = 0; j < DH; j++) {
        float pv = g_pool[b * DH + j];
        for (int c = 0; c < NCLS; c++) z[c] = fmaf(pv, linW[j * NCLS + c], z[c]);
    }
    float m = fmaxf(z[0], fmaxf(z[1], z[2]));
    float s = expf(z[0] - m) + expf(z[1] - m) + expf(z[2] - m);
    float lse = m + logf(s);
    for (int c = 0; c < NCLS; c++) out[b * NCLS + c] = z[c] - lse;
}

// ---------------- launcher ----------------
extern "C" void kernel_launch(void* const* d_in, const int* in_sizes, int n_in,
                              void* d_out, int out_size) {
    const float* x      = (const float*)d_in[0];
    const int*   ei     = (const int*)  d_in[1];
    const int*   batch  = (const int*)  d_in[2];
    const float* topk_w = (const float*)d_in[3];
    const float* W1 = (const float*)d_in[4],  *b1 = (const float*)d_in[5];
    const float* g1 = (const float*)d_in[6],  *be1= (const float*)d_in[7];
    const float* rm1= (const float*)d_in[8],  *rv1= (const float*)d_in[9];
    const float* W2 = (const float*)d_in[10], *b2 = (const float*)d_in[11];
    const float* g2 = (const float*)d_in[12], *be2= (const float*)d_in[13];
    const float* rm2= (const float*)d_in[14], *rv2= (const float*)d_in[15];
    const float* W3 = (const float*)d_in[16], *b3 = (const float*)d_in[17];
    const float* g3 = (const float*)d_in[18], *be3= (const float*)d_in[19];
    const float* rm3= (const float*)d_in[20], *rv3= (const float*)d_in[21];
    const float* linW = (const float*)d_in[22];
    const float* linb = (const float*)d_in[23];
    float* out = (float*)d_out;

    const int NT = 256;
    const int GN = (NN + NT - 1) / NT;          // 391
    const int GE = (EE + NT - 1) / NT;          // 6250
    const int GS = 592;                         // stride-loop grid (4*148)

    float *hA, *hB;
    cudaGetSymbolAddress((void**)&hA, g_hA);
    cudaGetSymbolAddress((void**)&hB, g_hB);

    k_init<<<GN, NT>>>();
    k_logit<<<GN, NT>>>(x, topk_w, batch);
    k_exp<<<GN, NT>>>(batch);
    k_score<<<GN, NT>>>(batch);
    k_keep<<<GN, NT>>>(x, batch);
    k_edges<<<GE, NT>>>(ei);
    k_dinv<<<GS, NT>>>();

    // layer 1 (din=2)
    float* h0;
    cudaGetSymbolAddress((void**)&h0, g_h0);
    k_aggself<2><<<GS, NT>>>(h0);
    k_aggedge<2><<<GS, NT>>>(h0);
    k_gemm1<<<1024, DH>>>(W1, b1, g1, be1, rm1, rv1, hA);

    // layer 2
    k_aggself<DH><<<GS, NT>>>(hA);
    k_aggedge<DH><<<GS, NT>>>(hA);
    k_gemm128<<<1024, DH>>>(W2, b2, g2, be2, rm2, rv2, hB);

    // layer 3
    k_aggself<DH><<<GS, NT>>>(hB);
    k_aggedge<DH><<<GS, NT>>>(hB);
    k_gemm128<<<1024, DH>>>(W3, b3, g3, be3, rm3, rv3, hA);

    k_pool<<<GS, NT>>>(batch, hA);
    k_final<<<1, BB>>>(linW, linb, out);
}

// round 2
// speedup vs baseline: 3.4020x; 3.4020x over previous
#include <cuda_runtime.h>
#include <math.h>
#include <float.h>

#define NN 100000
#define BB 64
#define EE 1600000
#define DH 128
#define NCLS 3
#define TOLV 1e-7f
#define BN_EPSV 1e-5f
#define MIN_SCORE 0.1f
#define KBWORDS ((NN + 31) / 32)

#define GRID 148
#define NT 256
#define TOT (GRID * NT)

// ---------------- persistent device scratch ----------------
__device__ unsigned g_bar_count = 0;
__device__ unsigned g_bar_gen = 0;

__device__ int   g_nk;
__device__ int   g_nce;
__device__ float g_logit[NN];
__device__ int   g_kidx[NN];
__device__ int   g_cidx[NN];
__device__ unsigned g_kbits[KBWORDS];
__device__ float g_h0[NN * 2];
__device__ int   g_esrc[EE];
__device__ int   g_edst[EE];
__device__ float g_degc[NN];
__device__ float g_agg[NN * DH];
__device__ float g_hA[NN * DH];
__device__ float g_hB[NN * DH];
__device__ float g_pool[BB * DH];

__device__ __forceinline__ void atomicMaxF(float* addr, float v) {
    if (v >= 0.0f) atomicMax((int*)addr, __float_as_int(v));
    else           atomicMin((unsigned int*)addr, __float_as_uint(v));
}

// Software grid barrier. All GRID blocks are co-resident (1 block/SM).
__device__ __forceinline__ void grid_barrier() {
    __syncthreads();
    if (threadIdx.x == 0) {
        unsigned gen = atomicAdd(&g_bar_gen, 0u);   // read generation BEFORE arriving
        __threadfence();                            // flush this block's writes
        unsigned ticket = atomicAdd(&g_bar_count, 1u);
        if (ticket == GRID - 1) {
            g_bar_count = 0;                        // reset before release
            __threadfence();
            atomicAdd(&g_bar_gen, 1u);              // release
        } else {
            while (atomicAdd(&g_bar_gen, 0u) == gen) { __nanosleep(64); }
        }
    }
    __syncthreads();
    __threadfence();
}

__device__ __forceinline__ int lbound_batch(const int* __restrict__ batch, int val) {
    int lo = 0, hi = NN;
    while (lo < hi) {
        int mid = (lo + hi) >> 1;
        if (batch[mid] < val) lo = mid + 1; else hi = mid;
    }
    return lo;
}

// layers 2/3: agg (self + optional edges) then 128x128 gemm + bias/relu/bn
__device__ void layer128(int tid, int nk, int nce,
                         const float* __restrict__ hin, float* __restrict__ hout,
                         const float* __restrict__ W, const float* __restrict__ b,
                         const float* __restrict__ g, const float* __restrict__ be,
                         const float* __restrict__ rm, const float* __restrict__ rv) {
    for (int t = tid; t < nk * DH; t += TOT) {
        int p = t >> 7;
        g_agg[t] = hin[t] / (g_degc[p] + 1.0f);        // self-loop norm = dinv^2
    }
    grid_barrier();
    if (nce > 0) {
        for (int t = tid; t < nce * DH; t += TOT) {
            int e = t >> 7, j = t & 127;
            int cs = g_esrc[e], cd = g_edst[e];
            float w = rsqrtf(g_degc[cs] + 1.0f) * rsqrtf(g_degc[cd] + 1.0f);
            atomicAdd(&g_agg[cd * DH + j], w * hin[cs * DH + j]);
        }
        grid_barrier();
    }
    for (int o = tid; o < nk * DH; o += TOT) {
        int p = o >> 7, j = o & 127;
        const float* arow = &g_agg[p * DH];
        float v = b[j];
        #pragma unroll 16
        for (int k = 0; k < DH; k++) v = fmaf(arow[k], W[k * DH + j], v);
        v = fmaxf(v, 0.0f);
        v = (v - rm[j]) * rsqrtf(rv[j] + BN_EPSV) * g[j] + be[j];
        hout[o] = v;
    }
    grid_barrier();
}

__global__ void __launch_bounds__(NT, 1) mega_kernel(
    const float* __restrict__ x, const int* __restrict__ ei,
    const int* __restrict__ batch, const float* __restrict__ tw,
    const float* __restrict__ W1, const float* __restrict__ b1,
    const float* __restrict__ g1, const float* __restrict__ be1,
    const float* __restrict__ rm1, const float* __restrict__ rv1,
    const float* __restrict__ W2, const float* __restrict__ b2,
    const float* __restrict__ g2, const float* __restrict__ be2,
    const float* __restrict__ rm2, const float* __restrict__ rv2,
    const float* __restrict__ W3, const float* __restrict__ b3,
    const float* __restrict__ g3, const float* __restrict__ be3,
    const float* __restrict__ rm3, const float* __restrict__ rv3,
    const float* __restrict__ linW, const float* __restrict__ linb,
    float* __restrict__ out) {

    const int tid = blockIdx.x * NT + threadIdx.x;

    // ---- phase 0: init ----
    for (int i = tid; i < KBWORDS; i += TOT) g_kbits[i] = 0u;
    for (int i = tid; i < BB * DH; i += TOT) g_pool[i] = -FLT_MAX;
    if (tid == 0) { g_nk = 0; g_nce = 0; }
    grid_barrier();

    // ---- phase 1: per-graph softmax + keep + compact (1 block / graph) ----
    if (blockIdx.x < BB) {
        __shared__ float red[NT];
        const int b = blockIdx.x;
        const int lo = lbound_batch(batch, b);
        const int hi = lbound_batch(batch, b + 1);

        // max logit
        float m = -FLT_MAX;
        for (int i = lo + threadIdx.x; i < hi; i += NT) {
            float l = x[2 * i] * tw[0] + x[2 * i + 1] * tw[1];
            g_logit[i] = l;
            m = fmaxf(m, l);
        }
        red[threadIdx.x] = m; __syncthreads();
        for (int s = NT / 2; s > 0; s >>= 1) {
            if (threadIdx.x < s) red[threadIdx.x] = fmaxf(red[threadIdx.x], red[threadIdx.x + s]);
            __syncthreads();
        }
        m = red[0]; __syncthreads();

        // sum of exp
        float sum = 0.0f;
        for (int i = lo + threadIdx.x; i < hi; i += NT) sum += expf(g_logit[i] - m);
        red[threadIdx.x] = sum; __syncthreads();
        for (int s = NT / 2; s > 0; s >>= 1) {
            if (threadIdx.x < s) red[threadIdx.x] += red[threadIdx.x + s];
            __syncthreads();
        }
        sum = red[0]; __syncthreads();

        // smax = (max e)/sum = 1/sum exactly (max node has e = exp(0) = 1)
        const float thr = fminf(1.0f / sum - TOLV, MIN_SCORE);
        for (int i = lo + threadIdx.x; i < hi; i += NT) {
            float s = expf(g_logit[i] - m) / sum;
            if (s > thr) {
                int pos = atomicAdd(&g_nk, 1);
                g_kidx[pos] = i;
                g_cidx[i] = pos;
                atomicOr(&g_kbits[i >> 5], 1u << (i & 31));
                g_h0[2 * pos + 0] = x[2 * i + 0] * s;
                g_h0[2 * pos + 1] = x[2 * i + 1] * s;
                g_degc[pos] = 0.0f;
            }
        }
    }
    grid_barrier();
    const int nk = *(volatile int*)&g_nk;

    // ---- phase 2: edge scan + compact ----
    #pragma unroll 4
    for (int e = tid; e < EE; e += TOT) {
        int s = ei[e];
        int d = ei[EE + e];
        if ((g_kbits[s >> 5] >> (s & 31)) & (g_kbits[d >> 5] >> (d & 31)) & 1u) {
            int pos = atomicAdd(&g_nce, 1);
            int cs = g_cidx[s], cd = g_cidx[d];
            g_esrc[pos] = cs;
            g_edst[pos] = cd;
            atomicAdd(&g_degc[cd], 1.0f);
        }
    }
    grid_barrier();
    const int nce = *(volatile int*)&g_nce;

    // ---- layer 1 (din = 2) ----
    for (int t = tid; t < nk * 2; t += TOT) {
        int p = t >> 1;
        g_agg[t] = g_h0[t] / (g_degc[p] + 1.0f);
    }
    grid_barrier();
    if (nce > 0) {
        for (int t = tid; t < nce * 2; t += TOT) {
            int e = t >> 1, j = t & 1;
            int cs = g_esrc[e], cd = g_edst[e];
            float w = rsqrtf(g_degc[cs] + 1.0f) * rsqrtf(g_degc[cd] + 1.0f);
            atomicAdd(&g_agg[cd * 2 + j], w * g_h0[cs * 2 + j]);
        }
        grid_barrier();
    }
    for (int o = tid; o < nk * DH; o += TOT) {
        int p = o >> 7, j = o & 127;
        float v = g_agg[2 * p] * W1[j] + g_agg[2 * p + 1] * W1[DH + j] + b1[j];
        v = fmaxf(v, 0.0f);
        v = (v - rm1[j]) * rsqrtf(rv1[j] + BN_EPSV) * g1[j] + be1[j];
        g_hA[o] = v;
    }
    grid_barrier();

    // ---- layers 2, 3 ----
    layer128(tid, nk, nce, g_hA, g_hB, W2, b2, g2, be2, rm2, rv2);
    layer128(tid, nk, nce, g_hB, g_hA, W3, b3, g3, be3, rm3, rv3);

    // ---- pool (max over kept nodes per graph) ----
    for (int t = tid; t < nk * DH; t += TOT) {
        int p = t >> 7, j = t & 127;
        atomicMaxF(&g_pool[batch[g_kidx[p]] * DH + j], g_hA[t]);
    }
    grid_barrier();

    // ---- final linear + log_softmax ----
    if (tid < BB) {
        int b = tid;
        float z[NCLS];
        #pragma unroll
        for (int c = 0; c < NCLS; c++) z[c] = linb[c];
        for (int j = 0; j < DH; j++) {
            float pv = g_pool[b * DH + j];
            #pragma unroll
            for (int c = 0; c < NCLS; c++) z[c] = fmaf(pv, linW[j * NCLS + c], z[c]);
        }
        float mm = fmaxf(z[0], fmaxf(z[1], z[2]));
        float s = expf(z[0] - mm) + expf(z[1] - mm) + expf(z[2] - mm);
        float lse = mm + logf(s);
        #pragma unroll
        for (int c = 0; c < NCLS; c++) out[b * NCLS + c] = z[c] - lse;
    }
}

// ---------------- launcher ----------------
extern "C" void kernel_launch(void* const* d_in, const int* in_sizes, int n_in,
                              void* d_out, int out_size) {
    const float* x      = (const float*)d_in[0];
    const int*   ei     = (const int*)  d_in[1];
    const int*   batch  = (const int*)  d_in[2];
    const float* topk_w = (const float*)d_in[3];
    const float* W1 = (const float*)d_in[4],  *b1 = (const float*)d_in[5];
    const float* g1 = (const float*)d_in[6],  *be1= (const float*)d_in[7];
    const float* rm1= (const float*)d_in[8],  *rv1= (const float*)d_in[9];
    const float* W2 = (const float*)d_in[10], *b2 = (const float*)d_in[11];
    const float* g2 = (const float*)d_in[12], *be2= (const float*)d_in[13];
    const float* rm2= (const float*)d_in[14], *rv2= (const float*)d_in[15];
    const float* W3 = (const float*)d_in[16], *b3 = (const float*)d_in[17];
    const float* g3 = (const float*)d_in[18], *be3= (const float*)d_in[19];
    const float* rm3= (const float*)d_in[20], *rv3= (const float*)d_in[21];
    const float* linW = (const float*)d_in[22];
    const float* linb = (const float*)d_in[23];
    float* out = (float*)d_out;

    mega_kernel<<<GRID, NT>>>(x, ei, batch, topk_w,
                              W1, b1, g1, be1, rm1, rv1,
                              W2, b2, g2, be2, rm2, rv2,
                              W3, b3, g3, be3, rm3, rv3,
                              linW, linb, out);
}

// round 3
// speedup vs baseline: 4.4467x; 1.3071x over previous
#include <cuda_runtime.h>
#include <math.h>
#include <float.h>

#define NN 100000
#define BB 64
#define EE 1600000
#define DH 128
#define NCLS 3
#define TOLV 1e-7f
#define BN_EPSV 1e-5f
#define MIN_SCORE 0.1f
#define KBWORDS ((NN + 31) / 32)

#define GRID 148
#define NT 512
#define TOT (GRID * NT)
#define CAP 2048            // shared-memory softmax capacity per graph

// ---------------- persistent device scratch ----------------
__device__ unsigned g_bar_count = 0;
__device__ unsigned g_bar_gen = 0;

__device__ int   g_nk;
__device__ int   g_nce;
__device__ int   g_start[BB + 1];
__device__ float g_logit[NN];         // fallback softmax path only
__device__ int   g_kidx[NN];          // compact pos -> node id (unused downstream but kept)
__device__ int   g_kgraph[NN];        // compact pos -> graph id
__device__ int   g_cidx[NN];
__device__ unsigned g_kbits[KBWORDS];
__device__ float g_h0[NN * 2];
__device__ int   g_esrc[EE];
__device__ int   g_edst[EE];
__device__ float g_degc[NN];
__device__ float g_agg[NN * DH];
__device__ float g_hA[NN * DH];
__device__ float g_hB[NN * DH];
__device__ float g_pool[BB * DH];

__device__ __forceinline__ void atomicMaxF(float* addr, float v) {
    if (v >= 0.0f) atomicMax((int*)addr, __float_as_int(v));
    else           atomicMin((unsigned int*)addr, __float_as_uint(v));
}

// Software grid barrier; all GRID blocks co-resident (1 block/SM).
__device__ __forceinline__ void grid_barrier() {
    __syncthreads();
    if (threadIdx.x == 0) {
        unsigned gen = *(volatile unsigned*)&g_bar_gen;   // read BEFORE arriving
        __threadfence();                                  // release prior writes
        unsigned ticket = atomicAdd(&g_bar_count, 1u);
        if (ticket == GRID - 1) {
            g_bar_count = 0;
            __threadfence();
            atomicAdd(&g_bar_gen, 1u);                    // release
        } else {
            unsigned g;
            do {
                __nanosleep(32);
                asm volatile("ld.acquire.gpu.u32 %0, [%1];"
                             : "=r"(g) : "l"(&g_bar_gen) : "memory");
            } while (g == gen);
        }
    }
    __syncthreads();   // block-wide propagation of thread 0's acquire
}

// ---------------- block reductions (shared red[32]) ----------------
__device__ __forceinline__ float blk_max(float v, float* red) {
    for (int o = 16; o > 0; o >>= 1) v = fmaxf(v, __shfl_xor_sync(~0u, v, o));
    if ((threadIdx.x & 31) == 0) red[threadIdx.x >> 5] = v;
    __syncthreads();
    if (threadIdx.x < 32) {
        float w = (threadIdx.x < NT / 32) ? red[threadIdx.x] : -FLT_MAX;
        for (int o = 16; o > 0; o >>= 1) w = fmaxf(w, __shfl_xor_sync(~0u, w, o));
        if (threadIdx.x == 0) red[0] = w;
    }
    __syncthreads();
    float r = red[0];
    __syncthreads();
    return r;
}
__device__ __forceinline__ float blk_sum(float v, float* red) {
    for (int o = 16; o > 0; o >>= 1) v += __shfl_xor_sync(~0u, v, o);
    if ((threadIdx.x & 31) == 0) red[threadIdx.x >> 5] = v;
    __syncthreads();
    if (threadIdx.x < 32) {
        float w = (threadIdx.x < NT / 32) ? red[threadIdx.x] : 0.0f;
        for (int o = 16; o > 0; o >>= 1) w += __shfl_xor_sync(~0u, w, o);
        if (threadIdx.x == 0) red[0] = w;
    }
    __syncthreads();
    float r = red[0];
    __syncthreads();
    return r;
}

// One GCN layer (128->128) + bias/relu/bn, optional pooled epilogue.
__device__ void gcn_layer128(int tid, int nk, int nce,
                             const float* __restrict__ hin, float* __restrict__ hout,
                             const float* __restrict__ W, const float* __restrict__ b,
                             const float* __restrict__ g, const float* __restrict__ be,
                             const float* __restrict__ rm, const float* __restrict__ rv,
                             const int* __restrict__ batch, bool do_pool) {
    const bool fused = (nce == 0);
    if (!fused) {
        for (int t = tid; t < nk * DH; t += TOT) {
            int p = t >> 7;
            g_agg[t] = hin[t] / (g_degc[p] + 1.0f);
        }
        grid_barrier();
        for (int t = tid; t < nce * DH; t += TOT) {
            int e = t >> 7, j = t & 127;
            int cs = g_esrc[e], cd = g_edst[e];
            float w = rsqrtf(g_degc[cs] + 1.0f) * rsqrtf(g_degc[cd] + 1.0f);
            atomicAdd(&g_agg[cd * DH + j], w * hin[cs * DH + j]);
        }
        grid_barrier();
    }
    for (int o = tid; o < nk * DH; o += TOT) {
        int p = o >> 7, j = o & 127;
        const float* arow = fused ? &hin[p * DH] : &g_agg[p * DH];
        float v = 0.0f;
        #pragma unroll 16
        for (int k = 0; k < DH; k++) v = fmaf(arow[k], W[k * DH + j], v);
        if (fused) v /= (g_degc[p] + 1.0f);
        v += b[j];
        v = fmaxf(v, 0.0f);
        v = (v - rm[j]) * rsqrtf(rv[j] + BN_EPSV) * g[j] + be[j];
        if (do_pool) atomicMaxF(&g_pool[g_kgraph[p] * DH + j], v);
        else hout[o] = v;
    }
    grid_barrier();
}

__global__ void __launch_bounds__(NT, 1) mega_kernel(
    const float* __restrict__ x, const int* __restrict__ ei,
    const int* __restrict__ batch, const float* __restrict__ tw,
    const float* __restrict__ W1, const float* __restrict__ b1,
    const float* __restrict__ g1, const float* __restrict__ be1,
    const float* __restrict__ rm1, const float* __restrict__ rv1,
    const float* __restrict__ W2, const float* __restrict__ b2,
    const float* __restrict__ g2, const float* __restrict__ be2,
    const float* __restrict__ rm2, const float* __restrict__ rv2,
    const float* __restrict__ W3, const float* __restrict__ b3,
    const float* __restrict__ g3, const float* __restrict__ be3,
    const float* __restrict__ rm3, const float* __restrict__ rv3,
    const float* __restrict__ linW, const float* __restrict__ linb,
    float* __restrict__ out) {

    __shared__ float s_logit[CAP];
    __shared__ float s_red[32];

    const int tid = blockIdx.x * NT + threadIdx.x;

    // ---- phase 0: init + graph boundary detection (one streaming pass) ----
    for (int i = tid; i < KBWORDS; i += TOT) g_kbits[i] = 0u;
    for (int i = tid; i < BB * DH; i += TOT) g_pool[i] = -FLT_MAX;
    if (tid == 0) { g_nk = 0; g_nce = 0; }
    for (int i = tid; i < NN; i += TOT) {
        int bi = batch[i];
        if (i == 0) {
            for (int b = 0; b <= bi; b++) g_start[b] = 0;
        } else {
            int bp = batch[i - 1];
            for (int b = bp + 1; b <= bi; b++) g_start[b] = i;
        }
        if (i == NN - 1) {
            for (int b = bi + 1; b <= BB; b++) g_start[b] = NN;
        }
    }
    grid_barrier();   // B1

    // ---- phase 1: per-graph softmax + keep + compact (1 block / graph) ----
    if (blockIdx.x < BB) {
        const int b = blockIdx.x;
        const int lo = g_start[b];
        const int hi = g_start[b + 1];
        const int cnt = hi - lo;
        const float tw0 = tw[0], tw1 = tw[1];

        if (cnt > 0 && cnt <= CAP) {
            float m = -FLT_MAX;
            for (int i = threadIdx.x; i < cnt; i += NT) {
                float2 xv = ((const float2*)x)[lo + i];
                float l = xv.x * tw0 + xv.y * tw1;
                s_logit[i] = l;
                m = fmaxf(m, l);
            }
            m = blk_max(m, s_red);
            float sum = 0.0f;
            for (int i = threadIdx.x; i < cnt; i += NT) {
                float e = expf(s_logit[i] - m);
                s_logit[i] = e;
                sum += e;
            }
            sum = blk_sum(sum, s_red);
            const float thr = fminf(1.0f / sum - TOLV, MIN_SCORE);
            for (int i = threadIdx.x; i < cnt; i += NT) {
                float s = s_logit[i] / sum;
                if (s > thr) {
                    int node = lo + i;
                    int pos = atomicAdd(&g_nk, 1);
                    g_kidx[pos] = node;
                    g_kgraph[pos] = b;
                    g_cidx[node] = pos;
                    atomicOr(&g_kbits[node >> 5], 1u << (node & 31));
                    float2 xv = ((const float2*)x)[node];
                    g_h0[2 * pos + 0] = xv.x * s;
                    g_h0[2 * pos + 1] = xv.y * s;
                    g_degc[pos] = 0.0f;
                }
            }
        } else if (cnt > 0) {
            // fallback: large graph, use global logit buffer
            float m = -FLT_MAX;
            for (int i = lo + threadIdx.x; i < hi; i += NT) {
                float2 xv = ((const float2*)x)[i];
                float l = xv.x * tw0 + xv.y * tw1;
                g_logit[i] = l;
                m = fmaxf(m, l);
            }
            m = blk_max(m, s_red);
            float sum = 0.0f;
            for (int i = lo + threadIdx.x; i < hi; i += NT)
                sum += expf(g_logit[i] - m);
            sum = blk_sum(sum, s_red);
            const float thr = fminf(1.0f / sum - TOLV, MIN_SCORE);
            for (int i = lo + threadIdx.x; i < hi; i += NT) {
                float s = expf(g_logit[i] - m) / sum;
                if (s > thr) {
                    int pos = atomicAdd(&g_nk, 1);
                    g_kidx[pos] = i;
                    g_kgraph[pos] = b;
                    g_cidx[i] = pos;
                    atomicOr(&g_kbits[i >> 5], 1u << (i & 31));
                    float2 xv = ((const float2*)x)[i];
                    g_h0[2 * pos + 0] = xv.x * s;
                    g_h0[2 * pos + 1] = xv.y * s;
                    g_degc[pos] = 0.0f;
                }
            }
        }
    }
    grid_barrier();   // B2
    const int nk = *(volatile int*)&g_nk;

    // ---- phase 2: vectorized edge scan + compact ----
    {
        const int4* s4 = (const int4*)ei;
        const int4* d4 = (const int4*)(ei + EE);
        for (int q = tid; q < EE / 4; q += TOT) {
            int4 ss = __ldg(&s4[q]);
            int4 dd = __ldg(&d4[q]);
            #pragma unroll
            for (int u = 0; u < 4; u++) {
                int s = (u == 0) ? ss.x : (u == 1) ? ss.y : (u == 2) ? ss.z : ss.w;
                int d = (u == 0) ? dd.x : (u == 1) ? dd.y : (u == 2) ? dd.z : dd.w;
                if ((g_kbits[s >> 5] >> (s & 31)) & (g_kbits[d >> 5] >> (d & 31)) & 1u) {
                    int pos = atomicAdd(&g_nce, 1);
                    g_esrc[pos] = g_cidx[s];
                    g_edst[pos] = g_cidx[d];
                    atomicAdd(&g_degc[g_cidx[d]], 1.0f);
                }
            }
        }
    }
    grid_barrier();   // B3
    const int nce = *(volatile int*)&g_nce;

    // ---- layer 1 (din = 2) ----
    if (nce == 0) {
        for (int o = tid; o < nk * DH; o += TOT) {
            int p = o >> 7, j = o & 127;
            float inv = 1.0f / (g_degc[p] + 1.0f);
            float v = inv * (g_h0[2 * p] * W1[j] + g_h0[2 * p + 1] * W1[DH + j]) + b1[j];
            v = fmaxf(v, 0.0f);
            v = (v - rm1[j]) * rsqrtf(rv1[j] + BN_EPSV) * g1[j] + be1[j];
            g_hA[o] = v;
        }
        grid_barrier();   // B4
    } else {
        for (int t = tid; t < nk * 2; t += TOT) {
            int p = t >> 1;
            g_agg[t] = g_h0[t] / (g_degc[p] + 1.0f);
        }
        grid_barrier();
        for (int t = tid; t < nce * 2; t += TOT) {
            int e = t >> 1, j = t & 1;
            int cs = g_esrc[e], cd = g_edst[e];
            float w = rsqrtf(g_degc[cs] + 1.0f) * rsqrtf(g_degc[cd] + 1.0f);
            atomicAdd(&g_agg[cd * 2 + j], w * g_h0[cs * 2 + j]);
        }
        grid_barrier();
        for (int o = tid; o < nk * DH; o += TOT) {
            int p = o >> 7, j = o & 127;
            float v = g_agg[2 * p] * W1[j] + g_agg[2 * p + 1] * W1[DH + j] + b1[j];
            v = fmaxf(v, 0.0f);
            v = (v - rm1[j]) * rsqrtf(rv1[j] + BN_EPSV) * g1[j] + be1[j];
            g_hA[o] = v;
        }
        grid_barrier();   // B4
    }

    // ---- layers 2, 3 (layer 3 pools directly) ----
    gcn_layer128(tid, nk, nce, g_hA, g_hB, W2, b2, g2, be2, rm2, rv2, batch, false); // B5
    gcn_layer128(tid, nk, nce, g_hB, g_hA, W3, b3, g3, be3, rm3, rv3, batch, true);  // B6

    // ---- final linear + log_softmax (block 0) ----
    if (tid < BB) {
        int b = tid;
        float z[NCLS];
        #pragma unroll
        for (int c = 0; c < NCLS; c++) z[c] = linb[c];
        for (int j = 0; j < DH; j++) {
            float pv = g_pool[b * DH + j];
            #pragma unroll
            for (int c = 0; c < NCLS; c++) z[c] = fmaf(pv, linW[j * NCLS + c], z[c]);
        }
        float mm = fmaxf(z[0], fmaxf(z[1], z[2]));
        float s = expf(z[0] - mm) + expf(z[1] - mm) + expf(z[2] - mm);
        float lse = mm + logf(s);
        #pragma unroll
        for (int c = 0; c < NCLS; c++) out[b * NCLS + c] = z[c] - lse;
    }
}

// ---------------- launcher ----------------
extern "C" void kernel_launch(void* const* d_in, const int* in_sizes, int n_in,
                              void* d_out, int out_size) {
    const float* x      = (const float*)d_in[0];
    const int*   ei     = (const int*)  d_in[1];
    const int*   batch  = (const int*)  d_in[2];
    const float* topk_w = (const float*)d_in[3];
    const float* W1 = (const float*)d_in[4],  *b1 = (const float*)d_in[5];
    const float* g1 = (const float*)d_in[6],  *be1= (const float*)d_in[7];
    const float* rm1= (const float*)d_in[8],  *rv1= (const float*)d_in[9];
    const float* W2 = (const float*)d_in[10], *b2 = (const float*)d_in[11];
    const float* g2 = (const float*)d_in[12], *be2= (const float*)d_in[13];
    const float* rm2= (const float*)d_in[14], *rv2= (const float*)d_in[15];
    const float* W3 = (const float*)d_in[16], *b3 = (const float*)d_in[17];
    const float* g3 = (const float*)d_in[18], *be3= (const float*)d_in[19];
    const float* rm3= (const float*)d_in[20], *rv3= (const float*)d_in[21];
    const float* linW = (const float*)d_in[22];
    const float* linb = (const float*)d_in[23];
    float* out = (float*)d_out;

    mega_kernel<<<GRID, NT>>>(x, ei, batch, topk_w,
                              W1, b1, g1, be1, rm1, rv1,
                              W2, b2, g2, be2, rm2, rv2,
                              W3, b3, g3, be3, rm3, rv3,
                              linW, linb, out);
}

// round 4
// speedup vs baseline: 4.5468x; 1.0225x over previous
#include <cuda_runtime.h>
#include <math.h>
#include <float.h>

#define NN 100000
#define BB 64
#define EE 1600000
#define DH 128
#define NCLS 3
#define TOLV 1e-7f
#define BN_EPSV 1e-5f
#define MIN_SCORE 0.1f
#define KBWORDS ((NN + 31) / 32)

#define GRID 148
#define NT 1024
#define TOT (GRID * NT)
#define CAP 2048            // shared-memory softmax capacity per graph
#define SUB (NT / DH)       // 8 nodes per block in fused MLP

// ---------------- persistent device scratch ----------------
__device__ unsigned g_bar_count = 0;
__device__ unsigned g_bar_gen = 0;

__device__ int   g_nk;
__device__ int   g_nce;
__device__ int   g_start[BB + 1];
__device__ float g_logit[NN];         // fallback softmax path only
__device__ int   g_kgraph[NN];        // compact pos -> graph id
__device__ int   g_cidx[NN];
__device__ unsigned g_kbits[KBWORDS];
__device__ float g_h0[NN * 2];
__device__ int   g_esrc[EE];
__device__ int   g_edst[EE];
__device__ float g_degc[NN];
__device__ float g_agg[NN * DH];
__device__ float g_hA[NN * DH];
__device__ float g_hB[NN * DH];
__device__ float g_pool[BB * DH];

__device__ __forceinline__ void atomicMaxF(float* addr, float v) {
    if (v >= 0.0f) atomicMax((int*)addr, __float_as_int(v));
    else           atomicMin((unsigned int*)addr, __float_as_uint(v));
}

// Software grid barrier; all GRID blocks co-resident (1 block/SM).
__device__ __forceinline__ void grid_barrier() {
    __syncthreads();
    if (threadIdx.x == 0) {
        unsigned gen = *(volatile unsigned*)&g_bar_gen;   // read BEFORE arriving
        __threadfence();                                  // release prior writes
        unsigned ticket = atomicAdd(&g_bar_count, 1u);
        if (ticket == GRID - 1) {
            g_bar_count = 0;
            __threadfence();
            atomicAdd(&g_bar_gen, 1u);                    // release
        } else {
            unsigned g;
            do {
                __nanosleep(32);
                asm volatile("ld.acquire.gpu.u32 %0, [%1];"
                             : "=r"(g) : "l"(&g_bar_gen) : "memory");
            } while (g == gen);
        }
    }
    __syncthreads();
}

// ---------------- block reductions (shared red[32]) ----------------
__device__ __forceinline__ float blk_max(float v, float* red) {
    for (int o = 16; o > 0; o >>= 1) v = fmaxf(v, __shfl_xor_sync(~0u, v, o));
    if ((threadIdx.x & 31) == 0) red[threadIdx.x >> 5] = v;
    __syncthreads();
    if (threadIdx.x < 32) {
        float w = (threadIdx.x < NT / 32) ? red[threadIdx.x] : -FLT_MAX;
        for (int o = 16; o > 0; o >>= 1) w = fmaxf(w, __shfl_xor_sync(~0u, w, o));
        if (threadIdx.x == 0) red[0] = w;
    }
    __syncthreads();
    float r = red[0];
    __syncthreads();
    return r;
}
__device__ __forceinline__ float blk_sum(float v, float* red) {
    for (int o = 16; o > 0; o >>= 1) v += __shfl_xor_sync(~0u, v, o);
    if ((threadIdx.x & 31) == 0) red[threadIdx.x >> 5] = v;
    __syncthreads();
    if (threadIdx.x < 32) {
        float w = (threadIdx.x < NT / 32) ? red[threadIdx.x] : 0.0f;
        for (int o = 16; o > 0; o >>= 1) w += __shfl_xor_sync(~0u, w, o);
        if (threadIdx.x == 0) red[0] = w;
    }
    __syncthreads();
    float r = red[0];
    __syncthreads();
    return r;
}

// General-path GCN layer (128->128) + bias/relu/bn (used only when nce > 0).
__device__ void gcn_layer128(int tid, int nk, int nce,
                             const float* __restrict__ hin, float* __restrict__ hout,
                             const float* __restrict__ W, const float* __restrict__ b,
                             const float* __restrict__ g, const float* __restrict__ be,
                             const float* __restrict__ rm, const float* __restrict__ rv,
                             bool do_pool) {
    for (int t = tid; t < nk * DH; t += TOT) {
        int p = t >> 7;
        g_agg[t] = hin[t] / (g_degc[p] + 1.0f);
    }
    grid_barrier();
    for (int t = tid; t < nce * DH; t += TOT) {
        int e = t >> 7, j = t & 127;
        int cs = g_esrc[e], cd = g_edst[e];
        float w = rsqrtf(g_degc[cs] + 1.0f) * rsqrtf(g_degc[cd] + 1.0f);
        atomicAdd(&g_agg[cd * DH + j], w * hin[cs * DH + j]);
    }
    grid_barrier();
    for (int o = tid; o < nk * DH; o += TOT) {
        int p = o >> 7, j = o & 127;
        const float* arow = &g_agg[p * DH];
        float v = b[j];
        #pragma unroll 16
        for (int k = 0; k < DH; k++) v = fmaf(arow[k], W[k * DH + j], v);
        v = fmaxf(v, 0.0f);
        v = (v - rm[j]) * rsqrtf(rv[j] + BN_EPSV) * g[j] + be[j];
        if (do_pool) atomicMaxF(&g_pool[g_kgraph[p] * DH + j], v);
        else hout[o] = v;
    }
    grid_barrier();
}

__global__ void __launch_bounds__(NT, 1) mega_kernel(
    const float* __restrict__ x, const int* __restrict__ ei,
    const int* __restrict__ batch, const float* __restrict__ tw,
    const float* __restrict__ W1, const float* __restrict__ b1,
    const float* __restrict__ g1, const float* __restrict__ be1,
    const float* __restrict__ rm1, const float* __restrict__ rv1,
    const float* __restrict__ W2, const float* __restrict__ b2,
    const float* __restrict__ g2, const float* __restrict__ be2,
    const float* __restrict__ rm2, const float* __restrict__ rv2,
    const float* __restrict__ W3, const float* __restrict__ b3,
    const float* __restrict__ g3, const float* __restrict__ be3,
    const float* __restrict__ rm3, const float* __restrict__ rv3,
    const float* __restrict__ linW, const float* __restrict__ linb,
    float* __restrict__ out) {

    __shared__ float s_logit[CAP];
    __shared__ float s_red[32];
    __shared__ float s_h[SUB][DH];

    const int tid = blockIdx.x * NT + threadIdx.x;

    // ---- phase 0: init + graph boundary detection ----
    for (int i = tid; i < KBWORDS; i += TOT) g_kbits[i] = 0u;
    for (int i = tid; i < BB * DH; i += TOT) g_pool[i] = -FLT_MAX;
    if (tid == 0) { g_nk = 0; g_nce = 0; }
    for (int i = tid; i < NN; i += TOT) {
        int bi = batch[i];
        if (i == 0) {
            for (int b = 0; b <= bi; b++) g_start[b] = 0;
        } else {
            int bp = batch[i - 1];
            for (int b = bp + 1; b <= bi; b++) g_start[b] = i;
        }
        if (i == NN - 1) {
            for (int b = bi + 1; b <= BB; b++) g_start[b] = NN;
        }
    }
    grid_barrier();   // B1

    // ---- phase 1: per-graph softmax + keep + compact (1 block / graph) ----
    if (blockIdx.x < BB) {
        const int b = blockIdx.x;
        const int lo = g_start[b];
        const int hi = g_start[b + 1];
        const int cnt = hi - lo;
        const float tw0 = tw[0], tw1 = tw[1];

        if (cnt > 0 && cnt <= CAP) {
            float m = -FLT_MAX;
            for (int i = threadIdx.x; i < cnt; i += NT) {
                float2 xv = ((const float2*)x)[lo + i];
                float l = xv.x * tw0 + xv.y * tw1;
                s_logit[i] = l;
                m = fmaxf(m, l);
            }
            m = blk_max(m, s_red);
            float sum = 0.0f;
            for (int i = threadIdx.x; i < cnt; i += NT) {
                float e = expf(s_logit[i] - m);
                s_logit[i] = e;
                sum += e;
            }
            sum = blk_sum(sum, s_red);
            const float thr = fminf(1.0f / sum - TOLV, MIN_SCORE);
            for (int i = threadIdx.x; i < cnt; i += NT) {
                float s = s_logit[i] / sum;
                if (s > thr) {
                    int node = lo + i;
                    int pos = atomicAdd(&g_nk, 1);
                    g_kgraph[pos] = b;
                    g_cidx[node] = pos;
                    atomicOr(&g_kbits[node >> 5], 1u << (node & 31));
                    float2 xv = ((const float2*)x)[node];
                    g_h0[2 * pos + 0] = xv.x * s;
                    g_h0[2 * pos + 1] = xv.y * s;
                    g_degc[pos] = 0.0f;
                }
            }
        } else if (cnt > 0) {
            float m = -FLT_MAX;
            for (int i = lo + threadIdx.x; i < hi; i += NT) {
                float2 xv = ((const float2*)x)[i];
                float l = xv.x * tw0 + xv.y * tw1;
                g_logit[i] = l;
                m = fmaxf(m, l);
            }
            m = blk_max(m, s_red);
            float sum = 0.0f;
            for (int i = lo + threadIdx.x; i < hi; i += NT)
                sum += expf(g_logit[i] - m);
            sum = blk_sum(sum, s_red);
            const float thr = fminf(1.0f / sum - TOLV, MIN_SCORE);
            for (int i = lo + threadIdx.x; i < hi; i += NT) {
                float s = expf(g_logit[i] - m) / sum;
                if (s > thr) {
                    int pos = atomicAdd(&g_nk, 1);
                    g_kgraph[pos] = b;
                    g_cidx[i] = pos;
                    atomicOr(&g_kbits[i >> 5], 1u << (i & 31));
                    float2 xv = ((const float2*)x)[i];
                    g_h0[2 * pos + 0] = xv.x * s;
                    g_h0[2 * pos + 1] = xv.y * s;
                    g_degc[pos] = 0.0f;
                }
            }
        }
    }
    grid_barrier();   // B2
    const int nk = *(volatile int*)&g_nk;

    // ---- phase 2: lazy-dst edge scan (read dst only when src is kept) ----
    {
        const int4* s4 = (const int4*)ei;
        const int*  dArr = ei + EE;
        for (int q = tid; q < EE / 4; q += TOT) {
            int4 ss = __ldg(&s4[q]);
            #pragma unroll
            for (int u = 0; u < 4; u++) {
                int s = (u == 0) ? ss.x : (u == 1) ? ss.y : (u == 2) ? ss.z : ss.w;
                if ((g_kbits[s >> 5] >> (s & 31)) & 1u) {
                    int d = __ldg(&dArr[4 * q + u]);
                    if ((g_kbits[d >> 5] >> (d & 31)) & 1u) {
                        int pos = atomicAdd(&g_nce, 1);
                        g_esrc[pos] = g_cidx[s];
                        g_edst[pos] = g_cidx[d];
                        atomicAdd(&g_degc[g_cidx[d]], 1.0f);
                    }
                }
            }
        }
    }
    grid_barrier();   // B3
    const int nce = *(volatile int*)&g_nce;

    if (nce == 0) {
        // ---- fused 3-layer per-node MLP + pool (degc == 0 -> norm == 1) ----
        const int sub = threadIdx.x >> 7;
        const int j = threadIdx.x & 127;
        for (int base = blockIdx.x * SUB; base < nk; base += GRID * SUB) {
            const int p = base + sub;
            const bool act = (p < nk);
            if (act) {
                float v = g_h0[2 * p] * W1[j] + g_h0[2 * p + 1] * W1[DH + j] + b1[j];
                v = fmaxf(v, 0.0f);
                v = (v - rm1[j]) * rsqrtf(rv1[j] + BN_EPSV) * g1[j] + be1[j];
                s_h[sub][j] = v;
            }
            __syncthreads();
            float v2 = b2[j];
            if (act) {
                #pragma unroll 16
                for (int k = 0; k < DH; k++) v2 = fmaf(s_h[sub][k], W2[k * DH + j], v2);
                v2 = fmaxf(v2, 0.0f);
                v2 = (v2 - rm2[j]) * rsqrtf(rv2[j] + BN_EPSV) * g2[j] + be2[j];
            }
            __syncthreads();
            if (act) s_h[sub][j] = v2;
            __syncthreads();
            if (act) {
                float v3 = b3[j];
                #pragma unroll 16
                for (int k = 0; k < DH; k++) v3 = fmaf(s_h[sub][k], W3[k * DH + j], v3);
                v3 = fmaxf(v3, 0.0f);
                v3 = (v3 - rm3[j]) * rsqrtf(rv3[j] + BN_EPSV) * g3[j] + be3[j];
                atomicMaxF(&g_pool[g_kgraph[p] * DH + j], v3);
            }
            __syncthreads();
        }
        grid_barrier();   // B4
    } else {
        // ---- general path with edge aggregation ----
        for (int t = tid; t < nk * 2; t += TOT) {
            int p = t >> 1;
            g_agg[t] = g_h0[t] / (g_degc[p] + 1.0f);
        }
        grid_barrier();
        for (int t = tid; t < nce * 2; t += TOT) {
            int e = t >> 1, j = t & 1;
            int cs = g_esrc[e], cd = g_edst[e];
            float w = rsqrtf(g_degc[cs] + 1.0f) * rsqrtf(g_degc[cd] + 1.0f);
            atomicAdd(&g_agg[cd * 2 + j], w * g_h0[cs * 2 + j]);
        }
        grid_barrier();
        for (int o = tid; o < nk * DH; o += TOT) {
            int p = o >> 7, j = o & 127;
            float v = g_agg[2 * p] * W1[j] + g_agg[2 * p + 1] * W1[DH + j] + b1[j];
            v = fmaxf(v, 0.0f);
            v = (v - rm1[j]) * rsqrtf(rv1[j] + BN_EPSV) * g1[j] + be1[j];
            g_hA[o] = v;
        }
        grid_barrier();
        gcn_layer128(tid, nk, nce, g_hA, g_hB, W2, b2, g2, be2, rm2, rv2, false);
        gcn_layer128(tid, nk, nce, g_hB, g_hA, W3, b3, g3, be3, rm3, rv3, true);
    }

    // ---- final linear + log_softmax ----
    if (tid < BB) {
        int b = tid;
        float z[NCLS];
        #pragma unroll
        for (int c = 0; c < NCLS; c++) z[c] = linb[c];
        for (int j = 0; j < DH; j++) {
            float pv = g_pool[b * DH + j];
            #pragma unroll
            for (int c = 0; c < NCLS; c++) z[c] = fmaf(pv, linW[j * NCLS + c], z[c]);
        }
        float mm = fmaxf(z[0], fmaxf(z[1], z[2]));
        float s = expf(z[0] - mm) + expf(z[1] - mm) + expf(z[2] - mm);
        float lse = mm + logf(s);
        #pragma unroll
        for (int c = 0; c < NCLS; c++) out[b * NCLS + c] = z[c] - lse;
    }
}

// ---------------- launcher ----------------
extern "C" void kernel_launch(void* const* d_in, const int* in_sizes, int n_in,
                              void* d_out, int out_size) {
    const float* x      = (const float*)d_in[0];
    const int*   ei     = (const int*)  d_in[1];
    const int*   batch  = (const int*)  d_in[2];
    const float* topk_w = (const float*)d_in[3];
    const float* W1 = (const float*)d_in[4],  *b1 = (const float*)d_in[5];
    const float* g1 = (const float*)d_in[6],  *be1= (const float*)d_in[7];
    const float* rm1= (const float*)d_in[8],  *rv1= (const float*)d_in[9];
    const float* W2 = (const float*)d_in[10], *b2 = (const float*)d_in[11];
    const float* g2 = (const float*)d_in[12], *be2= (const float*)d_in[13];
    const float* rm2= (const float*)d_in[14], *rv2= (const float*)d_in[15];
    const float* W3 = (const float*)d_in[16], *b3 = (const float*)d_in[17];
    const float* g3 = (const float*)d_in[18], *be3= (const float*)d_in[19];
    const float* rm3= (const float*)d_in[20], *rv3= (const float*)d_in[21];
    const float* linW = (const float*)d_in[22];
    const float* linb = (const float*)d_in[23];
    float* out = (float*)d_out;

    mega_kernel<<<GRID, NT>>>(x, ei, batch, topk_w,
                              W1, b1, g1, be1, rm1, rv1,
                              W2, b2, g2, be2, rm2, rv2,
                              W3, b3, g3, be3, rm3, rv3,
                              linW, linb, out);
}